// round 12
// baseline (speedup 1.0000x reference)
#include <cuda_runtime.h>
#include <math.h>
#include <stdint.h>

// Problem dims
#define Bn   64
#define Sn   512
#define En   512
#define Hn   256
#define G4   1024   // 4*H
#define HID  512
#define ATTn 256
#define Cn   10
#define Mrows 32768 // S*B == B*S
#define CLU  8      // cluster size for LSTM

// ------------------------- scratch (static device globals) -------------------------
__device__ float g_embed[Mrows][En];           // 64 MB: materialized gather
__device__ float g_gx[2][Sn][Bn][G4];          // 256 MB: precomputed input-gate projections
__device__ float g_lstm[Bn][Sn][HID];          // 64 MB: bilstm output
__device__ float g_T[Mrows][ATTn];             // 32 MB: tanh(att1) activations
__device__ float g_scores[Bn * Sn];
__device__ float g_alpha[Bn * Sn];
__device__ float g_pooled[Bn][HID];

__device__ __forceinline__ float sigf(float x) { return 1.f / (1.f + expf(-x)); }

__device__ __forceinline__ uint32_t smem_u32(const void* p) {
    return (uint32_t)__cvta_generic_to_shared(p);
}
__device__ __forceinline__ void fma2(unsigned long long& acc, unsigned long long a, unsigned long long b) {
    asm volatile("fma.rn.f32x2 %0, %1, %2, %0;" : "+l"(acc) : "l"(a), "l"(b));
}

// ------------------------- embedding gather: g_embed[s*64+b] = emb[x[b,s]] -------------------------
__global__ __launch_bounds__(128) void gather_kernel(const int* __restrict__ x,
                                                     const float* __restrict__ emb)
{
    int row = blockIdx.x;               // row = s*64 + b
    int s = row >> 6, b = row & 63;
    int v = x[b * Sn + s];
    const float4* src = (const float4*)&emb[(size_t)v * En];
    float4* dst = (float4*)&g_embed[row][0];
    dst[threadIdx.x] = src[threadIdx.x];   // 128 * 16B = 2KB row
}

// ------------------------- GEMM 1: gx = g_embed @ w_ih^T + b_ih + b_hh -------------------------
// M=32768 (row = s*64+b), N=1024, K=512. BM=128, BN=128, BK=16, 256 threads, 8x8 microtile.
// Grid: x = n-tile (8), y = m-stripe (256), z = dir  -> co-resident blocks share the A stripe in L2.
__global__ __launch_bounds__(256) void gemm_gx_kernel(
    const float* __restrict__ wif, const float* __restrict__ bif, const float* __restrict__ bhf,
    const float* __restrict__ wib, const float* __restrict__ bib, const float* __restrict__ bhb)
{
    const int dir = blockIdx.z;
    const float* W  = dir ? wib : wif;
    const float* B1 = dir ? bib : bif;
    const float* B2 = dir ? bhb : bhf;
    float* OUT = &g_gx[dir][0][0][0];

    __shared__ float As[16][128];
    __shared__ float Ws[16][128];

    const int tid = threadIdx.x;
    const int n0 = blockIdx.x * 128;
    const int m0 = blockIdx.y * 128;
    const float* A = &g_embed[0][0];

    float acc[8][8];
    #pragma unroll
    for (int i = 0; i < 8; i++)
        #pragma unroll
        for (int j = 0; j < 8; j++) acc[i][j] = 0.f;

    const int rg = tid >> 4;   // 0..15
    const int cg = tid & 15;   // 0..15

    for (int k0 = 0; k0 < En; k0 += 16) {
        #pragma unroll
        for (int i = 0; i < 2; i++) {
            int e = tid + i * 256;               // 0..511 float4 slots
            int m = e >> 2;
            int k4 = (e & 3) * 4;
            float4 v = *reinterpret_cast<const float4*>(&A[(size_t)(m0 + m) * En + k0 + k4]);
            As[k4 + 0][m] = v.x; As[k4 + 1][m] = v.y; As[k4 + 2][m] = v.z; As[k4 + 3][m] = v.w;
        }
        #pragma unroll
        for (int i = 0; i < 2; i++) {
            int e = tid + i * 256;
            int n = e >> 2;
            int k4 = (e & 3) * 4;
            float4 v = *reinterpret_cast<const float4*>(&W[(size_t)(n0 + n) * En + k0 + k4]);
            Ws[k4 + 0][n] = v.x; Ws[k4 + 1][n] = v.y; Ws[k4 + 2][n] = v.z; Ws[k4 + 3][n] = v.w;
        }
        __syncthreads();
        #pragma unroll
        for (int k = 0; k < 16; k++) {
            float ra[8], rw[8];
            #pragma unroll
            for (int i = 0; i < 8; i++) ra[i] = As[k][rg * 8 + i];
            #pragma unroll
            for (int j = 0; j < 8; j++) rw[j] = Ws[k][cg * 8 + j];
            #pragma unroll
            for (int i = 0; i < 8; i++)
                #pragma unroll
                for (int j = 0; j < 8; j++) acc[i][j] += ra[i] * rw[j];
        }
        __syncthreads();
    }
    #pragma unroll
    for (int i = 0; i < 8; i++) {
        size_t r = (size_t)(m0 + rg * 8 + i);
        #pragma unroll
        for (int j = 0; j < 8; j++) {
            int n = n0 + cg * 8 + j;
            OUT[r * G4 + n] = acc[i][j] + B1[n] + B2[n];
        }
    }
}

// ------------------------- GEMM 2: T = tanh(lstm_out @ att1_w^T + b1) -------------------------
__global__ __launch_bounds__(256) void gemm_att_kernel(
    const float* __restrict__ W, const float* __restrict__ bias)
{
    __shared__ float As[16][128];
    __shared__ float Ws[16][128];

    const int tid = threadIdx.x;
    const int m0 = blockIdx.x * 128;
    const int n0 = blockIdx.y * 128;
    const float* A = &g_lstm[0][0][0];

    float acc[8][8];
    #pragma unroll
    for (int i = 0; i < 8; i++)
        #pragma unroll
        for (int j = 0; j < 8; j++) acc[i][j] = 0.f;

    const int rg = tid >> 4;
    const int cg = tid & 15;

    for (int k0 = 0; k0 < HID; k0 += 16) {
        #pragma unroll
        for (int i = 0; i < 2; i++) {
            int e = tid + i * 256;
            int m = e >> 2;
            int k4 = (e & 3) * 4;
            float4 v = *reinterpret_cast<const float4*>(&A[(size_t)(m0 + m) * HID + k0 + k4]);
            As[k4 + 0][m] = v.x; As[k4 + 1][m] = v.y; As[k4 + 2][m] = v.z; As[k4 + 3][m] = v.w;
        }
        #pragma unroll
        for (int i = 0; i < 2; i++) {
            int e = tid + i * 256;
            int n = e >> 2;
            int k4 = (e & 3) * 4;
            float4 v = *reinterpret_cast<const float4*>(&W[(size_t)(n0 + n) * HID + k0 + k4]);
            Ws[k4 + 0][n] = v.x; Ws[k4 + 1][n] = v.y; Ws[k4 + 2][n] = v.z; Ws[k4 + 3][n] = v.w;
        }
        __syncthreads();
        #pragma unroll
        for (int k = 0; k < 16; k++) {
            float ra[8], rw[8];
            #pragma unroll
            for (int i = 0; i < 8; i++) ra[i] = As[k][rg * 8 + i];
            #pragma unroll
            for (int j = 0; j < 8; j++) rw[j] = Ws[k][cg * 8 + j];
            #pragma unroll
            for (int i = 0; i < 8; i++)
                #pragma unroll
                for (int j = 0; j < 8; j++) acc[i][j] += ra[i] * rw[j];
        }
        __syncthreads();
    }
    #pragma unroll
    for (int i = 0; i < 8; i++) {
        int r = m0 + rg * 8 + i;
        #pragma unroll
        for (int j = 0; j < 8; j++) {
            int n = n0 + cg * 8 + j;
            g_T[r][n] = tanhf(acc[i][j] + bias[n]);
        }
    }
}

// ------------------------- LSTM: cluster-persistent, SMEM-resident weights -------------------------
// grid = (64, 2): x = bg*8 + rank (cluster of 8 along x), y = dir. 256 threads.
// Cluster (dir, bg) handles 8 batches. CTA rank r owns hidden units j in [r*32, r*32+32),
// keeps its 4 gates x 32 j x 256 k weights (130 KB, padded) in SMEM, computes gates for its
// 8 batches with packed f32x2 FMA, then broadcasts its 32 h-values per batch to all 8 CTAs
// via DSMEM. One cluster barrier per step; h double-buffered.
//
// Thread layout: tid = b*32 + j  (warp == batch, lane == j). Weight LDS: per 8-lane phase,
// 8 consecutive j at row stride 130 u64 (=4 banks) -> 32 distinct banks, conflict-free.
// h LDS: whole warp reads the same address -> broadcast. gx LDG: 128B contiguous per warp.
#define LSTM_W_U64   (4 * 32 * 130)                       // padded weights, in u64
#define LSTM_SMEM    (LSTM_W_U64 * 8 + 2 * 8 * 256 * 4)   // 133120 + 16384 = 149504 B

__global__ __launch_bounds__(256, 1) __cluster_dims__(CLU, 1, 1)
void lstm_cluster_kernel(const float* __restrict__ whf, const float* __restrict__ whb)
{
    extern __shared__ unsigned long long sm[];
    unsigned long long (*w2)[32][130] = (unsigned long long(*)[32][130])sm;
    float* hb = (float*)(sm + LSTM_W_U64);    // hbuf[2][8][256]

    const int dir = blockIdx.y;
    const int cx  = blockIdx.x;
    const int bg  = cx >> 3;      // batch group 0..7
    const int r   = cx & 7;       // cluster rank
    const int tid = threadIdx.x;
    const int b   = tid >> 5;     // 0..7
    const int j   = tid & 31;     // 0..31

    // Load this CTA's weight slice: rows gate*256 + r*32 + jj, k = 0..255
    const float* W = dir ? whb : whf;
    for (int e = tid; e < 4 * 32 * 64; e += 256) {   // float4 granularity
        int g  = e >> 11;
        int jj = (e >> 6) & 31;
        int c4 = e & 63;
        float4 v = *(const float4*)&W[(size_t)(g * 256 + r * 32 + jj) * 256 + c4 * 4];
        *(float4*)&w2[g][jj][c4 * 2] = v;
    }
    for (int e = tid; e < 2 * 8 * 256; e += 256) hb[e] = 0.f;
    __syncthreads();
    asm volatile("barrier.cluster.arrive.aligned;" ::: "memory");
    asm volatile("barrier.cluster.wait.aligned;"  ::: "memory");

    // DSMEM destinations: peer hbuf base addresses
    uint32_t hb_local = smem_u32(hb);
    uint32_t dst[CLU];
    #pragma unroll
    for (int p = 0; p < CLU; p++) {
        uint32_t a;
        asm("mapa.shared::cluster.u32 %0, %1, %2;" : "=r"(a) : "r"(hb_local), "r"(p));
        dst[p] = a;
    }

    const unsigned long long* wrow0 = &w2[0][j][0];
    const unsigned long long* wrow1 = &w2[1][j][0];
    const unsigned long long* wrow2 = &w2[2][j][0];
    const unsigned long long* wrow3 = &w2[3][j][0];

    const int bglob = bg * 8 + b;
    const float* gxbase = &g_gx[dir][0][0][0];
    float c = 0.f;
    int cur = 0;

    for (int t = 0; t < Sn; t++) {
        const int s = dir ? (Sn - 1 - t) : t;

        // prefetch gx early (DRAM latency hidden under the acc loop)
        const float* gp = gxbase + ((size_t)s * Bn + bglob) * G4 + r * 32 + j;
        float pre_i = gp[0 * Hn], pre_f = gp[1 * Hn], pre_g = gp[2 * Hn], pre_o = gp[3 * Hn];

        const ulonglong2* hp = (const ulonglong2*)(hb + (cur * 8 + b) * 256);
        const ulonglong2* p0 = (const ulonglong2*)wrow0;
        const ulonglong2* p1 = (const ulonglong2*)wrow1;
        const ulonglong2* p2 = (const ulonglong2*)wrow2;
        const ulonglong2* p3 = (const ulonglong2*)wrow3;

        unsigned long long ai = 0ull, af = 0ull, ag = 0ull, ao = 0ull;
        #pragma unroll 8
        for (int kq = 0; kq < 64; kq++) {
            ulonglong2 h2 = hp[kq];
            ulonglong2 v0 = p0[kq];
            ulonglong2 v1 = p1[kq];
            ulonglong2 v2 = p2[kq];
            ulonglong2 v3 = p3[kq];
            fma2(ai, v0.x, h2.x); fma2(ai, v0.y, h2.y);
            fma2(af, v1.x, h2.x); fma2(af, v1.y, h2.y);
            fma2(ag, v2.x, h2.x); fma2(ag, v2.y, h2.y);
            fma2(ao, v3.x, h2.x); fma2(ao, v3.y, h2.y);
        }

        float2 qi = *(float2*)&ai, qf = *(float2*)&af, qg = *(float2*)&ag, qo = *(float2*)&ao;
        float I = sigf(pre_i + qi.x + qi.y);
        float F = sigf(pre_f + qf.x + qf.y);
        float G = tanhf(pre_g + qg.x + qg.y);
        float O = sigf(pre_o + qo.x + qo.y);
        c = F * c + I * G;
        float h = O * tanhf(c);

        g_lstm[bglob][s][dir * Hn + r * 32 + j] = h;

        const int nxt = cur ^ 1;
        uint32_t off = (uint32_t)(((nxt * 8 + b) * 256 + r * 32 + j) * 4);
        #pragma unroll
        for (int p = 0; p < CLU; p++)
            asm volatile("st.shared::cluster.f32 [%0], %1;" :: "r"(dst[p] + off), "f"(h) : "memory");

        asm volatile("barrier.cluster.arrive.aligned;" ::: "memory");
        asm volatile("barrier.cluster.wait.aligned;"  ::: "memory");
        cur = nxt;
    }
}

// ------------------------- scores = T @ UT -------------------------
__global__ __launch_bounds__(256) void score_kernel(const float* __restrict__ UT)
{
    int row = blockIdx.x * 8 + (threadIdx.x >> 5);
    int lane = threadIdx.x & 31;
    float s = 0.f;
    #pragma unroll
    for (int i = 0; i < 8; i++) s += g_T[row][lane + i * 32] * UT[lane + i * 32];
    #pragma unroll
    for (int o = 16; o > 0; o >>= 1) s += __shfl_xor_sync(0xffffffffu, s, o);
    if (lane == 0) g_scores[row] = s;
}

// ------------------------- softmax over S per batch -------------------------
__global__ __launch_bounds__(512) void softmax_kernel(float* alpha_out)
{
    int b = blockIdx.x, s = threadIdx.x;
    float v = g_scores[b * Sn + s];
    __shared__ float red[16];

    float m = v;
    #pragma unroll
    for (int o = 16; o > 0; o >>= 1) m = fmaxf(m, __shfl_xor_sync(0xffffffffu, m, o));
    if ((s & 31) == 0) red[s >> 5] = m;
    __syncthreads();
    if (s < 32) {
        float t = (s < 16) ? red[s] : -3.4e38f;
        #pragma unroll
        for (int o = 8; o > 0; o >>= 1) t = fmaxf(t, __shfl_xor_sync(0xffffffffu, t, o));
        if (s == 0) red[0] = t;
    }
    __syncthreads();
    m = red[0];
    __syncthreads();

    float e = expf(v - m);
    float sum = e;
    #pragma unroll
    for (int o = 16; o > 0; o >>= 1) sum += __shfl_xor_sync(0xffffffffu, sum, o);
    if ((s & 31) == 0) red[s >> 5] = sum;
    __syncthreads();
    if (s < 32) {
        float t = (s < 16) ? red[s] : 0.f;
        #pragma unroll
        for (int o = 8; o > 0; o >>= 1) t += __shfl_xor_sync(0xffffffffu, t, o);
        if (s == 0) red[0] = t;
    }
    __syncthreads();
    float a = e / red[0];
    g_alpha[b * Sn + s] = a;
    if (alpha_out) alpha_out[b * Sn + s] = a;
}

// ------------------------- pooled = sum_s alpha[b,s] * lstm_out[b,s,:] -------------------------
__global__ __launch_bounds__(512) void pooled_kernel()
{
    int b = blockIdx.x, h = threadIdx.x;
    __shared__ float al[Sn];
    al[h] = g_alpha[b * Sn + h];
    __syncthreads();
    float acc = 0.f;
    #pragma unroll 8
    for (int s = 0; s < Sn; s++) acc += al[s] * g_lstm[b][s][h];
    g_pooled[b][h] = acc;
}

// ------------------------- logit = pooled @ att2_w^T + b2 -------------------------
__global__ __launch_bounds__(320) void logit_kernel(
    const float* __restrict__ w2, const float* __restrict__ b2, float* out)
{
    int b = blockIdx.x;
    int c = threadIdx.x >> 5;     // 0..9
    int lane = threadIdx.x & 31;
    float acc = 0.f;
    #pragma unroll
    for (int i = 0; i < 16; i++)
        acc += g_pooled[b][lane + i * 32] * w2[c * HID + lane + i * 32];
    #pragma unroll
    for (int o = 16; o > 0; o >>= 1) acc += __shfl_xor_sync(0xffffffffu, acc, o);
    if (lane == 0 && out) out[b * Cn + c] = acc + b2[c];
}

// ------------------------- launch -------------------------
extern "C" void kernel_launch(void* const* d_in, const int* in_sizes, int n_in,
                              void* d_out, int out_size)
{
    const int*   x   = (const int*)d_in[0];
    const float* emb = (const float*)d_in[1];
    const float* wif = (const float*)d_in[2];
    const float* whf = (const float*)d_in[3];
    const float* bif = (const float*)d_in[4];
    const float* bhf = (const float*)d_in[5];
    const float* wib = (const float*)d_in[6];
    const float* whb = (const float*)d_in[7];
    const float* bib = (const float*)d_in[8];
    const float* bhb = (const float*)d_in[9];
    const float* a1w = (const float*)d_in[10];
    const float* a1b = (const float*)d_in[11];
    const float* ut  = (const float*)d_in[12];
    const float* a2w = (const float*)d_in[13];
    const float* a2b = (const float*)d_in[14];
    float* out = (float*)d_out;

    // output layout: (logit[64*10], alpha[64*512]) flattened in tuple order
    float* logit_ptr = nullptr;
    float* alpha_ptr = nullptr;
    if (out_size >= Bn * Cn + Bn * Sn) { logit_ptr = out; alpha_ptr = out + Bn * Cn; }
    else if (out_size == Bn * Sn)      { alpha_ptr = out; }
    else                                { logit_ptr = out; }

    static int smem_set = 0;
    if (!smem_set) {
        cudaFuncSetAttribute(lstm_cluster_kernel,
                             cudaFuncAttributeMaxDynamicSharedMemorySize, LSTM_SMEM);
        smem_set = 1;
    }

    gather_kernel<<<Mrows, 128>>>(x, emb);
    gemm_gx_kernel<<<dim3(G4 / 128, Mrows / 128, 2), 256>>>(wif, bif, bhf, wib, bib, bhb);
    lstm_cluster_kernel<<<dim3(64, 2), 256, LSTM_SMEM>>>(whf, whb);
    gemm_att_kernel<<<dim3(Mrows / 128, ATTn / 128), 256>>>(a1w, a1b);
    score_kernel<<<Mrows / 8, 256>>>(ut);
    softmax_kernel<<<Bn, 512>>>(alpha_ptr);
    pooled_kernel<<<Bn, 512>>>();
    logit_kernel<<<Bn, 320>>>(a2w, a2b, logit_ptr);
}

// round 13
// speedup vs baseline: 1.0531x; 1.0531x over previous
#include <cuda_runtime.h>
#include <math.h>
#include <stdint.h>

// Problem dims
#define Bn   64
#define Sn   512
#define En   512
#define Hn   256
#define G4   1024   // 4*H
#define HID  512
#define ATTn 256
#define Cn   10
#define Mrows 32768 // S*B == B*S
#define CLU  8      // cluster size for LSTM

// ------------------------- scratch (static device globals) -------------------------
__device__ float g_embed[Mrows][En];           // 64 MB: materialized gather
__device__ float g_gx[2][Sn][Bn][G4];          // 256 MB: precomputed input-gate projections
__device__ float g_lstm[Bn][Sn][HID];          // 64 MB: bilstm output
__device__ float g_T[Mrows][ATTn];             // 32 MB: tanh(att1) activations
__device__ float g_scores[Bn * Sn];
__device__ float g_alpha[Bn * Sn];
__device__ float g_pooled[Bn][HID];

__device__ __forceinline__ float sigf(float x) { return 1.f / (1.f + expf(-x)); }

__device__ __forceinline__ uint32_t smem_u32(const void* p) {
    return (uint32_t)__cvta_generic_to_shared(p);
}
__device__ __forceinline__ void fma2(unsigned long long& acc, unsigned long long a, unsigned long long b) {
    asm volatile("fma.rn.f32x2 %0, %1, %2, %0;" : "+l"(acc) : "l"(a), "l"(b));
}

// ------------------------- embedding gather: g_embed[s*64+b] = emb[x[b,s]] -------------------------
__global__ __launch_bounds__(128) void gather_kernel(const int* __restrict__ x,
                                                     const float* __restrict__ emb)
{
    int row = blockIdx.x;               // row = s*64 + b
    int s = row >> 6, b = row & 63;
    int v = x[b * Sn + s];
    const float4* src = (const float4*)&emb[(size_t)v * En];
    float4* dst = (float4*)&g_embed[row][0];
    dst[threadIdx.x] = src[threadIdx.x];   // 128 * 16B = 2KB row
}

// ------------------------- GEMM 1: gx = g_embed @ w_ih^T + b_ih + b_hh -------------------------
// M=32768 (row = s*64+b), N=1024, K=512. BM=128, BN=128, BK=16, 256 threads, 8x8 microtile.
// Grid: x = n-tile (8), y = m-stripe (256), z = dir  -> co-resident blocks share the A stripe in L2.
__global__ __launch_bounds__(256) void gemm_gx_kernel(
    const float* __restrict__ wif, const float* __restrict__ bif, const float* __restrict__ bhf,
    const float* __restrict__ wib, const float* __restrict__ bib, const float* __restrict__ bhb)
{
    const int dir = blockIdx.z;
    const float* W  = dir ? wib : wif;
    const float* B1 = dir ? bib : bif;
    const float* B2 = dir ? bhb : bhf;
    float* OUT = &g_gx[dir][0][0][0];

    __shared__ float As[16][128];
    __shared__ float Ws[16][128];

    const int tid = threadIdx.x;
    const int n0 = blockIdx.x * 128;
    const int m0 = blockIdx.y * 128;
    const float* A = &g_embed[0][0];

    float acc[8][8];
    #pragma unroll
    for (int i = 0; i < 8; i++)
        #pragma unroll
        for (int j = 0; j < 8; j++) acc[i][j] = 0.f;

    const int rg = tid >> 4;   // 0..15
    const int cg = tid & 15;   // 0..15

    for (int k0 = 0; k0 < En; k0 += 16) {
        #pragma unroll
        for (int i = 0; i < 2; i++) {
            int e = tid + i * 256;               // 0..511 float4 slots
            int m = e >> 2;
            int k4 = (e & 3) * 4;
            float4 v = *reinterpret_cast<const float4*>(&A[(size_t)(m0 + m) * En + k0 + k4]);
            As[k4 + 0][m] = v.x; As[k4 + 1][m] = v.y; As[k4 + 2][m] = v.z; As[k4 + 3][m] = v.w;
        }
        #pragma unroll
        for (int i = 0; i < 2; i++) {
            int e = tid + i * 256;
            int n = e >> 2;
            int k4 = (e & 3) * 4;
            float4 v = *reinterpret_cast<const float4*>(&W[(size_t)(n0 + n) * En + k0 + k4]);
            Ws[k4 + 0][n] = v.x; Ws[k4 + 1][n] = v.y; Ws[k4 + 2][n] = v.z; Ws[k4 + 3][n] = v.w;
        }
        __syncthreads();
        #pragma unroll
        for (int k = 0; k < 16; k++) {
            float ra[8], rw[8];
            #pragma unroll
            for (int i = 0; i < 8; i++) ra[i] = As[k][rg * 8 + i];
            #pragma unroll
            for (int j = 0; j < 8; j++) rw[j] = Ws[k][cg * 8 + j];
            #pragma unroll
            for (int i = 0; i < 8; i++)
                #pragma unroll
                for (int j = 0; j < 8; j++) acc[i][j] += ra[i] * rw[j];
        }
        __syncthreads();
    }
    #pragma unroll
    for (int i = 0; i < 8; i++) {
        size_t r = (size_t)(m0 + rg * 8 + i);
        #pragma unroll
        for (int j = 0; j < 8; j++) {
            int n = n0 + cg * 8 + j;
            OUT[r * G4 + n] = acc[i][j] + B1[n] + B2[n];
        }
    }
}

// ------------------------- GEMM 2: T = tanh(lstm_out @ att1_w^T + b1) -------------------------
__global__ __launch_bounds__(256) void gemm_att_kernel(
    const float* __restrict__ W, const float* __restrict__ bias)
{
    __shared__ float As[16][128];
    __shared__ float Ws[16][128];

    const int tid = threadIdx.x;
    const int m0 = blockIdx.x * 128;
    const int n0 = blockIdx.y * 128;
    const float* A = &g_lstm[0][0][0];

    float acc[8][8];
    #pragma unroll
    for (int i = 0; i < 8; i++)
        #pragma unroll
        for (int j = 0; j < 8; j++) acc[i][j] = 0.f;

    const int rg = tid >> 4;
    const int cg = tid & 15;

    for (int k0 = 0; k0 < HID; k0 += 16) {
        #pragma unroll
        for (int i = 0; i < 2; i++) {
            int e = tid + i * 256;
            int m = e >> 2;
            int k4 = (e & 3) * 4;
            float4 v = *reinterpret_cast<const float4*>(&A[(size_t)(m0 + m) * HID + k0 + k4]);
            As[k4 + 0][m] = v.x; As[k4 + 1][m] = v.y; As[k4 + 2][m] = v.z; As[k4 + 3][m] = v.w;
        }
        #pragma unroll
        for (int i = 0; i < 2; i++) {
            int e = tid + i * 256;
            int n = e >> 2;
            int k4 = (e & 3) * 4;
            float4 v = *reinterpret_cast<const float4*>(&W[(size_t)(n0 + n) * HID + k0 + k4]);
            Ws[k4 + 0][n] = v.x; Ws[k4 + 1][n] = v.y; Ws[k4 + 2][n] = v.z; Ws[k4 + 3][n] = v.w;
        }
        __syncthreads();
        #pragma unroll
        for (int k = 0; k < 16; k++) {
            float ra[8], rw[8];
            #pragma unroll
            for (int i = 0; i < 8; i++) ra[i] = As[k][rg * 8 + i];
            #pragma unroll
            for (int j = 0; j < 8; j++) rw[j] = Ws[k][cg * 8 + j];
            #pragma unroll
            for (int i = 0; i < 8; i++)
                #pragma unroll
                for (int j = 0; j < 8; j++) acc[i][j] += ra[i] * rw[j];
        }
        __syncthreads();
    }
    #pragma unroll
    for (int i = 0; i < 8; i++) {
        int r = m0 + rg * 8 + i;
        #pragma unroll
        for (int j = 0; j < 8; j++) {
            int n = n0 + cg * 8 + j;
            g_T[r][n] = tanhf(acc[i][j] + bias[n]);
        }
    }
}

// ------------------------- LSTM: cluster-persistent, SMEM-resident weights -------------------------
// grid = (64, 2): x = bg*8 + rank (cluster of 8 along x), y = dir. 256 threads.
// Cluster (dir, bg) handles 8 batches. CTA rank r owns hidden units j in [r*32, r*32+32),
// keeps its 4 gates x 32 j x 256 k weights (130 KB, padded) in SMEM, computes gates for its
// 8 batches with packed f32x2 FMA, then broadcasts its 32 h-values per batch to all 8 CTAs
// via DSMEM. One cluster barrier per step; h double-buffered.
//
// Thread layout: tid = b*32 + j  (warp == batch, lane == j). Weight LDS: per 8-lane phase,
// 8 consecutive j at row stride 130 u64 (=4 banks) -> 32 distinct banks, conflict-free.
// h LDS: whole warp reads the same address -> broadcast. gx LDG: 128B contiguous per warp.
#define LSTM_W_U64   (4 * 32 * 130)                       // padded weights, in u64
#define LSTM_SMEM    (LSTM_W_U64 * 8 + 2 * 8 * 256 * 4)   // 133120 + 16384 = 149504 B

__global__ __launch_bounds__(256, 1) __cluster_dims__(CLU, 1, 1)
void lstm_cluster_kernel(const float* __restrict__ whf, const float* __restrict__ whb)
{
    extern __shared__ unsigned long long sm[];
    unsigned long long (*w2)[32][130] = (unsigned long long(*)[32][130])sm;
    float* hb = (float*)(sm + LSTM_W_U64);    // hbuf[2][8][256]

    const int dir = blockIdx.y;
    const int cx  = blockIdx.x;
    const int bg  = cx >> 3;      // batch group 0..7
    const int r   = cx & 7;       // cluster rank
    const int tid = threadIdx.x;
    const int b   = tid >> 5;     // 0..7
    const int j   = tid & 31;     // 0..31

    // Load this CTA's weight slice: rows gate*256 + r*32 + jj, k = 0..255
    const float* W = dir ? whb : whf;
    for (int e = tid; e < 4 * 32 * 64; e += 256) {   // float4 granularity
        int g  = e >> 11;
        int jj = (e >> 6) & 31;
        int c4 = e & 63;
        float4 v = *(const float4*)&W[(size_t)(g * 256 + r * 32 + jj) * 256 + c4 * 4];
        *(float4*)&w2[g][jj][c4 * 2] = v;
    }
    for (int e = tid; e < 2 * 8 * 256; e += 256) hb[e] = 0.f;
    __syncthreads();
    asm volatile("barrier.cluster.arrive.aligned;" ::: "memory");
    asm volatile("barrier.cluster.wait.aligned;"  ::: "memory");

    // DSMEM destinations: peer hbuf base addresses
    uint32_t hb_local = smem_u32(hb);
    uint32_t dst[CLU];
    #pragma unroll
    for (int p = 0; p < CLU; p++) {
        uint32_t a;
        asm("mapa.shared::cluster.u32 %0, %1, %2;" : "=r"(a) : "r"(hb_local), "r"(p));
        dst[p] = a;
    }

    const unsigned long long* wrow0 = &w2[0][j][0];
    const unsigned long long* wrow1 = &w2[1][j][0];
    const unsigned long long* wrow2 = &w2[2][j][0];
    const unsigned long long* wrow3 = &w2[3][j][0];

    const int bglob = bg * 8 + b;
    const float* gxbase = &g_gx[dir][0][0][0];
    float c = 0.f;
    int cur = 0;

    for (int t = 0; t < Sn; t++) {
        const int s = dir ? (Sn - 1 - t) : t;

        // prefetch gx early (DRAM latency hidden under the acc loop)
        const float* gp = gxbase + ((size_t)s * Bn + bglob) * G4 + r * 32 + j;
        float pre_i = gp[0 * Hn], pre_f = gp[1 * Hn], pre_g = gp[2 * Hn], pre_o = gp[3 * Hn];

        const ulonglong2* hp = (const ulonglong2*)(hb + (cur * 8 + b) * 256);
        const ulonglong2* p0 = (const ulonglong2*)wrow0;
        const ulonglong2* p1 = (const ulonglong2*)wrow1;
        const ulonglong2* p2 = (const ulonglong2*)wrow2;
        const ulonglong2* p3 = (const ulonglong2*)wrow3;

        unsigned long long ai = 0ull, af = 0ull, ag = 0ull, ao = 0ull;
        #pragma unroll 8
        for (int kq = 0; kq < 64; kq++) {
            ulonglong2 h2 = hp[kq];
            ulonglong2 v0 = p0[kq];
            ulonglong2 v1 = p1[kq];
            ulonglong2 v2 = p2[kq];
            ulonglong2 v3 = p3[kq];
            fma2(ai, v0.x, h2.x); fma2(ai, v0.y, h2.y);
            fma2(af, v1.x, h2.x); fma2(af, v1.y, h2.y);
            fma2(ag, v2.x, h2.x); fma2(ag, v2.y, h2.y);
            fma2(ao, v3.x, h2.x); fma2(ao, v3.y, h2.y);
        }

        float2 qi = *(float2*)&ai, qf = *(float2*)&af, qg = *(float2*)&ag, qo = *(float2*)&ao;
        float I = sigf(pre_i + qi.x + qi.y);
        float F = sigf(pre_f + qf.x + qf.y);
        float G = tanhf(pre_g + qg.x + qg.y);
        float O = sigf(pre_o + qo.x + qo.y);
        c = F * c + I * G;
        float h = O * tanhf(c);

        g_lstm[bglob][s][dir * Hn + r * 32 + j] = h;

        const int nxt = cur ^ 1;
        uint32_t off = (uint32_t)(((nxt * 8 + b) * 256 + r * 32 + j) * 4);
        #pragma unroll
        for (int p = 0; p < CLU; p++)
            asm volatile("st.shared::cluster.f32 [%0], %1;" :: "r"(dst[p] + off), "f"(h) : "memory");

        asm volatile("barrier.cluster.arrive.aligned;" ::: "memory");
        asm volatile("barrier.cluster.wait.aligned;"  ::: "memory");
        cur = nxt;
    }
}

// ------------------------- scores = T @ UT -------------------------
__global__ __launch_bounds__(256) void score_kernel(const float* __restrict__ UT)
{
    int row = blockIdx.x * 8 + (threadIdx.x >> 5);
    int lane = threadIdx.x & 31;
    float s = 0.f;
    #pragma unroll
    for (int i = 0; i < 8; i++) s += g_T[row][lane + i * 32] * UT[lane + i * 32];
    #pragma unroll
    for (int o = 16; o > 0; o >>= 1) s += __shfl_xor_sync(0xffffffffu, s, o);
    if (lane == 0) g_scores[row] = s;
}

// ------------------------- softmax over S per batch -------------------------
__global__ __launch_bounds__(512) void softmax_kernel(float* alpha_out)
{
    int b = blockIdx.x, s = threadIdx.x;
    float v = g_scores[b * Sn + s];
    __shared__ float red[16];

    float m = v;
    #pragma unroll
    for (int o = 16; o > 0; o >>= 1) m = fmaxf(m, __shfl_xor_sync(0xffffffffu, m, o));
    if ((s & 31) == 0) red[s >> 5] = m;
    __syncthreads();
    if (s < 32) {
        float t = (s < 16) ? red[s] : -3.4e38f;
        #pragma unroll
        for (int o = 8; o > 0; o >>= 1) t = fmaxf(t, __shfl_xor_sync(0xffffffffu, t, o));
        if (s == 0) red[0] = t;
    }
    __syncthreads();
    m = red[0];
    __syncthreads();

    float e = expf(v - m);
    float sum = e;
    #pragma unroll
    for (int o = 16; o > 0; o >>= 1) sum += __shfl_xor_sync(0xffffffffu, sum, o);
    if ((s & 31) == 0) red[s >> 5] = sum;
    __syncthreads();
    if (s < 32) {
        float t = (s < 16) ? red[s] : 0.f;
        #pragma unroll
        for (int o = 8; o > 0; o >>= 1) t += __shfl_xor_sync(0xffffffffu, t, o);
        if (s == 0) red[0] = t;
    }
    __syncthreads();
    float a = e / red[0];
    g_alpha[b * Sn + s] = a;
    if (alpha_out) alpha_out[b * Sn + s] = a;
}

// ------------------------- pooled = sum_s alpha[b,s] * lstm_out[b,s,:] -------------------------
__global__ __launch_bounds__(512) void pooled_kernel()
{
    int b = blockIdx.x, h = threadIdx.x;
    __shared__ float al[Sn];
    al[h] = g_alpha[b * Sn + h];
    __syncthreads();
    float acc = 0.f;
    #pragma unroll 8
    for (int s = 0; s < Sn; s++) acc += al[s] * g_lstm[b][s][h];
    g_pooled[b][h] = acc;
}

// ------------------------- logit = pooled @ att2_w^T + b2 -------------------------
__global__ __launch_bounds__(320) void logit_kernel(
    const float* __restrict__ w2, const float* __restrict__ b2, float* out)
{
    int b = blockIdx.x;
    int c = threadIdx.x >> 5;     // 0..9
    int lane = threadIdx.x & 31;
    float acc = 0.f;
    #pragma unroll
    for (int i = 0; i < 16; i++)
        acc += g_pooled[b][lane + i * 32] * w2[c * HID + lane + i * 32];
    #pragma unroll
    for (int o = 16; o > 0; o >>= 1) acc += __shfl_xor_sync(0xffffffffu, acc, o);
    if (lane == 0 && out) out[b * Cn + c] = acc + b2[c];
}

// ------------------------- launch -------------------------
extern "C" void kernel_launch(void* const* d_in, const int* in_sizes, int n_in,
                              void* d_out, int out_size)
{
    const int*   x   = (const int*)d_in[0];
    const float* emb = (const float*)d_in[1];
    const float* wif = (const float*)d_in[2];
    const float* whf = (const float*)d_in[3];
    const float* bif = (const float*)d_in[4];
    const float* bhf = (const float*)d_in[5];
    const float* wib = (const float*)d_in[6];
    const float* whb = (const float*)d_in[7];
    const float* bib = (const float*)d_in[8];
    const float* bhb = (const float*)d_in[9];
    const float* a1w = (const float*)d_in[10];
    const float* a1b = (const float*)d_in[11];
    const float* ut  = (const float*)d_in[12];
    const float* a2w = (const float*)d_in[13];
    const float* a2b = (const float*)d_in[14];
    float* out = (float*)d_out;

    // output layout: (logit[64*10], alpha[64*512]) flattened in tuple order
    float* logit_ptr = nullptr;
    float* alpha_ptr = nullptr;
    if (out_size >= Bn * Cn + Bn * Sn) { logit_ptr = out; alpha_ptr = out + Bn * Cn; }
    else if (out_size == Bn * Sn)      { alpha_ptr = out; }
    else                                { logit_ptr = out; }

    static int smem_set = 0;
    if (!smem_set) {
        cudaFuncSetAttribute(lstm_cluster_kernel,
                             cudaFuncAttributeMaxDynamicSharedMemorySize, LSTM_SMEM);
        smem_set = 1;
    }

    gather_kernel<<<Mrows, 128>>>(x, emb);
    gemm_gx_kernel<<<dim3(G4 / 128, Mrows / 128, 2), 256>>>(wif, bif, bhf, wib, bib, bhb);
    lstm_cluster_kernel<<<dim3(64, 2), 256, LSTM_SMEM>>>(whf, whb);
    gemm_att_kernel<<<dim3(Mrows / 128, ATTn / 128), 256>>>(a1w, a1b);
    score_kernel<<<Mrows / 8, 256>>>(ut);
    softmax_kernel<<<Bn, 512>>>(alpha_ptr);
    pooled_kernel<<<Bn, 512>>>();
    logit_kernel<<<Bn, 320>>>(a2w, a2b, logit_ptr);
}